// round 13
// baseline (speedup 1.0000x reference)
#include <cuda_runtime.h>
#include <cuda_fp16.h>
#include <cstdint>

#define NN 100000
#define NE 1000000
#define KF 128
#define HID 64
#define TROWS 128                     // rows per block-tile
#define GTILES 4                      // block-tiles per block (persistent)
#define NPART 98                      // scan partial blocks = ceil(NN/1024)

#define WS_STRIDE 72                  // 72 mod 32 == 8 -> W loads conflict-free
#define WS_BYTES (KF * WS_STRIDE * 4) // 36864
#define AS_BYTES (4 * TROWS * 12 * 4) // 24576
#define GEMM_SMEM (WS_BYTES + AS_BYTES)

// ---------------- scratch ----------------
__device__ float   g_H0[NN * HID];     // f32: exact per-node term
__device__ __half2 g_G1[NN * 32];      // H1 rows as 32 half2 (col pairs)
__device__ __half2 g_G2[NN * 32];      // H2 rows as 32 half2
__device__ float g_s00[NN];            // H0.Wa_top + H0.Wa_bot/3 + b_att
__device__ float g_sb1[NN];            // H1.Wa_bot/3
__device__ float g_sb2[NN];            // H2.Wa_bot/3
__device__ int   g_deg[NN];            // INVARIANT: zero at entry (agg re-zeroes)
__device__ int   g_offs[NN];           // exclusive offsets; end-offsets after edge pass
__device__ int   g_part[128];
__device__ int2  g_epack[NE];          // {i1, i2} in CSR order

// ---------------- helpers ----------------
__device__ __forceinline__ uint32_t tf32_rna(float x) {
    uint32_t u;
    asm("cvt.rna.tf32.f32 %0, %1;" : "=r"(u) : "f"(x));
    return u;
}
__device__ __forceinline__ float tanh_approx(float x) {
    float t;
    asm("tanh.approx.f32 %0, %1;" : "=f"(t) : "f"(x));
    return t;
}
__device__ __forceinline__ void cpa16(void* smem, const void* gmem) {
    unsigned s = (unsigned)__cvta_generic_to_shared(smem);
    asm volatile("cp.async.ca.shared.global [%0], [%1], 16;\n" :: "r"(s), "l"(gmem));
}

// ---------------- kernel 1: tf32 mma.sync GEMM ----------------
// 128 threads = 4 warps; per block-tile 128 rows x 64 cols; K=128, 16 chunks of 8.
// Per warp: 2 M-tiles (32 rows) x 8 N-tiles; W fragments reused across M-tiles.
__global__ void __launch_bounds__(128, 3) gemm_mma_kernel(
    const float* __restrict__ f0, const float* __restrict__ f1,
    const float* __restrict__ f2, const float* __restrict__ W,
    const float* __restrict__ b, const float* __restrict__ Wa,
    const float* __restrict__ b_att)
{
    extern __shared__ char dsm[];
    uint32_t (*Ws)[WS_STRIDE] = reinterpret_cast<uint32_t(*)[WS_STRIDE]>(dsm);
    float (*As)[TROWS][12] = reinterpret_cast<float(*)[TROWS][12]>(dsm + WS_BYTES);

    int fk = blockIdx.y;
    const float* feat = (fk == 0) ? f0 : ((fk == 1) ? f1 : f2);
    int tid = threadIdx.x;
    int wid = tid >> 5, lane = tid & 31;
    int qk = lane & 3;
    int qr = lane >> 2;
    int wl = wid * 32 + qr;            // first row of this warp's m-tile 0
    float ba = (fk == 0) ? __ldg(b_att) : 0.f;
    __half2* G = (fk == 1) ? g_G1 : g_G2;

    // stage W (tf32-rounded) once per block; stride-72 rows
#pragma unroll
    for (int i = 0; i < 64; i++) {
        int idx = tid + i * 128;
        Ws[idx >> 6][idx & 63] = tf32_rna(W[idx]);
    }
    __syncthreads();

    for (int t = 0; t < GTILES; t++) {
        int row0 = (blockIdx.x * GTILES + t) * TROWS;
        if (row0 >= NN) break;

        // cp.async: each thread covers 2 float4 per chunk (rows ra and 64+ra)
        int ra = tid >> 1, cc = (tid & 1) * 4;
        int gra = row0 + ra;       if (gra >= NN) gra = NN - 1;
        int grb = row0 + 64 + ra;  if (grb >= NN) grb = NN - 1;
        const float* psa = feat + (size_t)gra * KF + cc;
        const float* psb = feat + (size_t)grb * KF + cc;
        auto issue = [&](int c) {
            cpa16(&As[c & 3][ra][cc], psa + c * 8);
            cpa16(&As[c & 3][64 + ra][cc], psb + c * 8);
            asm volatile("cp.async.commit_group;\n");
        };

        issue(0); issue(1); issue(2);

        float acc[2][8][4];
#pragma unroll
        for (int mt = 0; mt < 2; mt++)
#pragma unroll
            for (int nt = 0; nt < 8; nt++)
#pragma unroll
                for (int j = 0; j < 4; j++) acc[mt][nt][j] = 0.f;

#pragma unroll
        for (int c = 0; c < 16; c++) {
            if (c < 14)       asm volatile("cp.async.wait_group 2;\n");
            else if (c == 14) asm volatile("cp.async.wait_group 1;\n");
            else              asm volatile("cp.async.wait_group 0;\n");
            __syncthreads();
            if (c + 3 < 16) issue(c + 3);
            int buf = c & 3;
            uint32_t a[2][4];
#pragma unroll
            for (int mt = 0; mt < 2; mt++) {
                int base = wl + mt * 16;
                a[mt][0] = tf32_rna(As[buf][base][qk]);
                a[mt][1] = tf32_rna(As[buf][base + 8][qk]);
                a[mt][2] = tf32_rna(As[buf][base][qk + 4]);
                a[mt][3] = tf32_rna(As[buf][base + 8][qk + 4]);
            }
            int k0 = c * 8;
#pragma unroll
            for (int nt = 0; nt < 8; nt++) {
                uint32_t b0 = Ws[k0 + qk][nt * 8 + qr];       // conflict-free (stride 72)
                uint32_t b1 = Ws[k0 + qk + 4][nt * 8 + qr];
                asm volatile(
                    "mma.sync.aligned.m16n8k8.row.col.f32.tf32.tf32.f32 "
                    "{%0,%1,%2,%3}, {%4,%5,%6,%7}, {%8,%9}, {%0,%1,%2,%3};"
                    : "+f"(acc[0][nt][0]), "+f"(acc[0][nt][1]), "+f"(acc[0][nt][2]), "+f"(acc[0][nt][3])
                    : "r"(a[0][0]), "r"(a[0][1]), "r"(a[0][2]), "r"(a[0][3]), "r"(b0), "r"(b1));
                asm volatile(
                    "mma.sync.aligned.m16n8k8.row.col.f32.tf32.tf32.f32 "
                    "{%0,%1,%2,%3}, {%4,%5,%6,%7}, {%8,%9}, {%0,%1,%2,%3};"
                    : "+f"(acc[1][nt][0]), "+f"(acc[1][nt][1]), "+f"(acc[1][nt][2]), "+f"(acc[1][nt][3])
                    : "r"(a[1][0]), "r"(a[1][1]), "r"(a[1][2]), "r"(a[1][3]), "r"(b0), "r"(b1));
            }
        }

        // epilogue per m-tile: bias add, store H, fused attention scalars
#pragma unroll
        for (int mt = 0; mt < 2; mt++) {
            int r  = row0 + wl + mt * 16;
            int r2 = r + 8;
            float pa = 0.f, pb = 0.f, pa2 = 0.f, pb2 = 0.f;
#pragma unroll
            for (int nt = 0; nt < 8; nt++) {
                int c = nt * 8 + 2 * qk;
                float2 bb = *reinterpret_cast<const float2*>(b + c);
                float2 wt = *reinterpret_cast<const float2*>(Wa + c);
                float2 wb = *reinterpret_cast<const float2*>(Wa + 64 + c);
                float o0 = acc[mt][nt][0] + bb.x, o1 = acc[mt][nt][1] + bb.y;
                float o2 = acc[mt][nt][2] + bb.x, o3 = acc[mt][nt][3] + bb.y;
                if (fk == 0) {
                    if (r < NN)
                        *reinterpret_cast<float2*>(g_H0 + (size_t)r * HID + c) = make_float2(o0, o1);
                    if (r2 < NN)
                        *reinterpret_cast<float2*>(g_H0 + (size_t)r2 * HID + c) = make_float2(o2, o3);
                } else {
                    if (r < NN)  G[r * 32 + (c >> 1)]  = __floats2half2_rn(o0, o1);
                    if (r2 < NN) G[r2 * 32 + (c >> 1)] = __floats2half2_rn(o2, o3);
                }
                pa  += o0 * wt.x + o1 * wt.y;  pb  += o0 * wb.x + o1 * wb.y;
                pa2 += o2 * wt.x + o3 * wt.y;  pb2 += o2 * wb.x + o3 * wb.y;
            }
#pragma unroll
            for (int off = 1; off <= 2; off <<= 1) {
                pa  += __shfl_xor_sync(0xffffffffu, pa,  off);
                pb  += __shfl_xor_sync(0xffffffffu, pb,  off);
                pa2 += __shfl_xor_sync(0xffffffffu, pa2, off);
                pb2 += __shfl_xor_sync(0xffffffffu, pb2, off);
            }
            if (qk == 0) {
                if (r < NN) {
                    if (fk == 0)      g_s00[r] = pa + pb * (1.0f / 3.0f) + ba;
                    else if (fk == 1) g_sb1[r] = pb * (1.0f / 3.0f);
                    else              g_sb2[r] = pb * (1.0f / 3.0f);
                }
                if (r2 < NN) {
                    if (fk == 0)      g_s00[r2] = pa2 + pb2 * (1.0f / 3.0f) + ba;
                    else if (fk == 1) g_sb1[r2] = pb2 * (1.0f / 3.0f);
                    else              g_sb2[r2] = pb2 * (1.0f / 3.0f);
                }
            }
        }
    }
}

// ---------------- kernel 2: degree histogram (deg pre-zeroed by agg tail) --------
__global__ void hist_kernel(const int* __restrict__ e0) {
    int i = blockIdx.x * blockDim.x + threadIdx.x;
    if (i < NE / 4) {
        int4 v = reinterpret_cast<const int4*>(e0)[i];
        atomicAdd(&g_deg[v.x], 1);
        atomicAdd(&g_deg[v.y], 1);
        atomicAdd(&g_deg[v.z], 1);
        atomicAdd(&g_deg[v.w], 1);
    }
}

// ---------------- kernel 3a: block-local scan, write partials ----------------
__global__ void scan1_kernel() {
    __shared__ int s[1024];
    int i = blockIdx.x * 1024 + threadIdx.x;
    int v = (i < NN) ? g_deg[i] : 0;
    s[threadIdx.x] = v;
    __syncthreads();
    for (int off = 1; off < 1024; off <<= 1) {
        int t = (threadIdx.x >= (unsigned)off) ? s[threadIdx.x - off] : 0;
        __syncthreads();
        s[threadIdx.x] += t;
        __syncthreads();
    }
    if (i < NN) g_offs[i] = s[threadIdx.x] - v;
    if (threadIdx.x == 1023) g_part[blockIdx.x] = s[1023];
}
// ---------------- kernel 3b: each block scans partials itself, adds prefix -------
__global__ void scan3_kernel() {
    __shared__ int s[128];
    int v = (threadIdx.x < NPART) ? g_part[threadIdx.x] : 0;
    s[threadIdx.x] = v;
    __syncthreads();
    for (int off = 1; off < 128; off <<= 1) {
        int t = (threadIdx.x >= (unsigned)off) ? s[threadIdx.x - off] : 0;
        __syncthreads();
        s[threadIdx.x] += t;
        __syncthreads();
    }
    __shared__ int prefix;
    if (threadIdx.x == (unsigned)blockIdx.x) prefix = s[threadIdx.x] - v;  // exclusive
    __syncthreads();
    int p = prefix;
#pragma unroll
    for (int q = 0; q < 8; q++) {
        int i = blockIdx.x * 1024 + q * 128 + threadIdx.x;
        if (i < NN) g_offs[i] += p;
    }
}

// ---------------- kernel 4: edge pass — pure CSR scatter of {i1,i2} --------------
__global__ void edge_kernel(const int* __restrict__ e0, const int* __restrict__ e1,
                            const int* __restrict__ e2) {
    int i = blockIdx.x * blockDim.x + threadIdx.x;
    if (i >= NE / 4) return;
    int4 a = reinterpret_cast<const int4*>(e0)[i];
    int4 b = reinterpret_cast<const int4*>(e1)[i];
    int4 c = reinterpret_cast<const int4*>(e2)[i];
#pragma unroll
    for (int q = 0; q < 4; q++) {
        int n  = (q == 0) ? a.x : (q == 1) ? a.y : (q == 2) ? a.z : a.w;
        int i1 = (q == 0) ? b.x : (q == 1) ? b.y : (q == 2) ? b.z : b.w;
        int i2 = (q == 0) ? c.x : (q == 1) ? c.y : (q == 2) ? c.z : c.w;
        int p = atomicAdd(&g_offs[n], 1);
        g_epack[p] = make_int2(i1, i2);
    }
}

// ---------------- kernel 5: aggregate — scores fused, batched prefetch + shfl ----
__global__ __launch_bounds__(256) void agg_kernel(const float* __restrict__ bias,
                                                  float* __restrict__ out) {
    int gw = (blockIdx.x * 256 + threadIdx.x) >> 5;
    int lane = threadIdx.x & 31;
    if (gw >= NN) return;
    int d = g_deg[gw];
    int start = g_offs[gw] - d;   // offs is end-offset after edge pass
    float2 bz = *reinterpret_cast<const float2*>(&bias[2 * lane]);
    float2 o;
    if (d == 0) {
        o = bz;
    } else {
        float s00 = g_s00[gw];    // once per node (broadcast load)
        float2 acc = make_float2(0.f, 0.f);
        float sumex = 0.f;
        for (int base = 0; base < d; base += 32) {
            int m = min(32, d - base);
            float myex = 0.f;
            int myi1 = 0, myi2 = 0;
            if (lane < m) {
                int2 rec = g_epack[start + base + lane];
                myi1 = rec.x;
                myi2 = rec.y;
                myex = __expf(tanh_approx(s00 + g_sb1[myi1] + g_sb2[myi2]));
            }
#pragma unroll 4
            for (int j = 0; j < m; j++) {
                float ex = __shfl_sync(0xffffffffu, myex, j);
                int i1   = __shfl_sync(0xffffffffu, myi1, j);
                int i2   = __shfl_sync(0xffffffffu, myi2, j);
                float2 f1 = __half22float2(g_G1[i1 * 32 + lane]);
                float2 f2 = __half22float2(g_G2[i2 * 32 + lane]);
                sumex += ex;
                acc.x += ex * (f1.x + f2.x);
                acc.y += ex * (f1.y + f2.y);
            }
        }
        float2 h0 = *reinterpret_cast<const float2*>(&g_H0[gw * HID + 2 * lane]);
        float inv = 1.0f / sumex;
        o.x = (h0.x + acc.x * inv) * (1.0f / 3.0f) + bz.x;
        o.y = (h0.y + acc.y * inv) * (1.0f / 3.0f) + bz.y;
    }
    *reinterpret_cast<float2*>(&out[gw * HID + 2 * lane]) = o;
    if (lane == 0) g_deg[gw] = 0;   // restore invariant for next replay
}

// ---------------- launch (fork-join: CSR chain overlaps GEMM) ----------------
extern "C" void kernel_launch(void* const* d_in, const int* in_sizes, int n_in,
                              void* d_out, int out_size) {
    const float* feats[3] = {0, 0, 0};
    const int* edges[3] = {0, 0, 0};
    const float *W_feat = 0, *b_feat = 0, *W_att = 0, *b_att = 0, *bias = 0;
    int nf = 0, ne = 0;
    for (int i = 0; i < n_in; i++) {
        int s = in_sizes[i];
        if (s == NN * KF) { if (nf < 3) feats[nf++] = (const float*)d_in[i]; }
        else if (s == NE) { if (ne < 3) edges[ne++] = (const int*)d_in[i]; }
        else if (s == KF * HID) W_feat = (const float*)d_in[i];
        else if (s == 2 * HID) W_att = (const float*)d_in[i];
        else if (s == HID) { if (!b_feat) b_feat = (const float*)d_in[i]; else bias = (const float*)d_in[i]; }
        else if (s == 1) b_att = (const float*)d_in[i];
    }
    float* out = (float*)d_out;

    static cudaStream_t s2 = 0;
    static cudaEvent_t ev_fork = 0, ev_join = 0;
    if (!s2) {
        cudaStreamCreateWithFlags(&s2, cudaStreamNonBlocking);
        cudaEventCreateWithFlags(&ev_fork, cudaEventDisableTiming);
        cudaEventCreateWithFlags(&ev_join, cudaEventDisableTiming);
        cudaFuncSetAttribute(gemm_mma_kernel,
                             cudaFuncAttributeMaxDynamicSharedMemorySize, GEMM_SMEM);
    }

    // fork: CSR chain on s2 (depends only on edge0; deg==0 invariant from agg tail)
    cudaEventRecord(ev_fork, 0);
    cudaStreamWaitEvent(s2, ev_fork, 0);
    hist_kernel<<<(NE / 4 + 255) / 256, 256, 0, s2>>>(edges[0]);
    scan1_kernel<<<NPART, 1024, 0, s2>>>();
    scan3_kernel<<<NPART, 128, 0, s2>>>();
    cudaEventRecord(ev_join, s2);

    // main stream: GEMM (depends only on feats/W)
    int gx = (NN + TROWS * GTILES - 1) / (TROWS * GTILES);
    gemm_mma_kernel<<<dim3(gx, 3), 128, GEMM_SMEM>>>(
        feats[0], feats[1], feats[2], W_feat, b_feat, W_att, b_att);

    // join, then edge + agg
    cudaStreamWaitEvent(0, ev_join, 0);
    edge_kernel<<<(NE / 4 + 255) / 256, 256>>>(edges[0], edges[1], edges[2]);
    agg_kernel<<<(NN * 32 + 255) / 256, 256>>>(bias, out);
}

// round 14
// speedup vs baseline: 1.3478x; 1.3478x over previous
#include <cuda_runtime.h>
#include <cuda_fp16.h>
#include <cstdint>

#define NN 100000
#define NE 1000000
#define KF 128
#define HID 64
#define GTILES 8                      // row-tiles (64 rows) per GEMM block
#define NPART 98                      // scan partial blocks = ceil(NN/1024)
#define WT_STRIDE 132                 // 132 mod 32 == 4 -> W frag loads conflict-free

// ---------------- scratch ----------------
__device__ float   g_H0[NN * HID];     // f32: exact per-node term
__device__ __half2 g_G1[NN * 32];      // H1 rows as 32 half2 (col pairs)
__device__ __half2 g_G2[NN * 32];      // H2 rows as 32 half2
__device__ float g_s00[NN];            // H0.Wa_top + H0.Wa_bot/3 + b_att
__device__ float g_sb1[NN];            // H1.Wa_bot/3
__device__ float g_sb2[NN];            // H2.Wa_bot/3
__device__ int   g_deg[NN];            // INVARIANT: zero at entry (agg re-zeroes)
__device__ int   g_offs[NN];           // exclusive offsets; end-offsets after edge pass
__device__ int   g_part[128];
__device__ int2  g_epack[NE];          // {i1, i2} in CSR order

// ---------------- helpers ----------------
__device__ __forceinline__ uint32_t tf32_rna(float x) {
    uint32_t u;
    asm("cvt.rna.tf32.f32 %0, %1;" : "=r"(u) : "f"(x));
    return u;
}
__device__ __forceinline__ float tanh_approx(float x) {
    float t;
    asm("tanh.approx.f32 %0, %1;" : "=f"(t) : "f"(x));
    return t;
}
__device__ __forceinline__ void cpa16(void* smem, const void* gmem) {
    unsigned s = (unsigned)__cvta_generic_to_shared(smem);
    asm volatile("cp.async.ca.shared.global [%0], [%1], 16;\n" :: "r"(s), "l"(gmem));
}

// ---------------- kernel 1: tf32 mma.sync GEMM (R12 structure, W transposed) -----
// 128 threads = 4 warps; per tile 64 rows x 64 cols; K=128, 16 chunks of 8.
__global__ void __launch_bounds__(128) gemm_mma_kernel(
    const float* __restrict__ f0, const float* __restrict__ f1,
    const float* __restrict__ f2, const float* __restrict__ W,
    const float* __restrict__ b, const float* __restrict__ Wa,
    const float* __restrict__ b_att)
{
    __shared__ uint32_t Wst[HID][WT_STRIDE];   // tf32 W^T[n][k]; frag bank=(4qr+qk): conflict-free
    __shared__ float As[4][64][12];            // conflict-free (12qr+qk distinct mod 32)

    int fk = blockIdx.y;
    const float* feat = (fk == 0) ? f0 : ((fk == 1) ? f1 : f2);
    int tid = threadIdx.x;
    int wid = tid >> 5, lane = tid & 31;
    int qk = lane & 3;
    int qr = lane >> 2;
    int wl = wid * 16 + qr;
    int crow = tid >> 1, ccol4 = tid & 1;
    float ba = (fk == 0) ? __ldg(b_att) : 0.f;
    __half2* G = (fk == 1) ? g_G1 : g_G2;

    // stage W transposed (tf32-rounded) once per block; coalesced global reads
#pragma unroll
    for (int i = 0; i < 64; i++) {
        int idx = tid + i * 128;               // 0..8191 over W[k][n]
        Wst[idx & 63][idx >> 6] = tf32_rna(W[idx]);
    }
    __syncthreads();

    for (int t = 0; t < GTILES; t++) {
        int row0 = (blockIdx.x * GTILES + t) * 64;
        if (row0 >= NN) break;

        int gr = row0 + crow;
        if (gr >= NN) gr = NN - 1;
        const float* csrc = feat + (size_t)gr * KF + ccol4 * 4;
        auto issue = [&](int c) {
            cpa16(&As[c & 3][crow][ccol4 * 4], csrc + c * 8);
            asm volatile("cp.async.commit_group;\n");
        };

        issue(0); issue(1); issue(2);

        float acc[8][4];
#pragma unroll
        for (int nt = 0; nt < 8; nt++)
#pragma unroll
            for (int j = 0; j < 4; j++) acc[nt][j] = 0.f;

#pragma unroll
        for (int c = 0; c < 16; c++) {
            if (c < 14)       asm volatile("cp.async.wait_group 2;\n");
            else if (c == 14) asm volatile("cp.async.wait_group 1;\n");
            else              asm volatile("cp.async.wait_group 0;\n");
            __syncthreads();
            if (c + 3 < 16) issue(c + 3);
            int buf = c & 3;
            uint32_t a0 = tf32_rna(As[buf][wl][qk]);
            uint32_t a1 = tf32_rna(As[buf][wl + 8][qk]);
            uint32_t a2 = tf32_rna(As[buf][wl][qk + 4]);
            uint32_t a3 = tf32_rna(As[buf][wl + 8][qk + 4]);
            int k0 = c * 8;
#pragma unroll
            for (int nt = 0; nt < 8; nt++) {
                uint32_t b0 = Wst[nt * 8 + qr][k0 + qk];
                uint32_t b1 = Wst[nt * 8 + qr][k0 + qk + 4];
                asm volatile(
                    "mma.sync.aligned.m16n8k8.row.col.f32.tf32.tf32.f32 "
                    "{%0,%1,%2,%3}, {%4,%5,%6,%7}, {%8,%9}, {%0,%1,%2,%3};"
                    : "+f"(acc[nt][0]), "+f"(acc[nt][1]), "+f"(acc[nt][2]), "+f"(acc[nt][3])
                    : "r"(a0), "r"(a1), "r"(a2), "r"(a3), "r"(b0), "r"(b1));
            }
        }

        int r  = row0 + wl;
        int r2 = r + 8;
        float pa = 0.f, pb = 0.f, pa2 = 0.f, pb2 = 0.f;
#pragma unroll
        for (int nt = 0; nt < 8; nt++) {
            int c = nt * 8 + 2 * qk;
            float2 bb = *reinterpret_cast<const float2*>(b + c);
            float2 wt = *reinterpret_cast<const float2*>(Wa + c);
            float2 wb = *reinterpret_cast<const float2*>(Wa + 64 + c);
            float o0 = acc[nt][0] + bb.x, o1 = acc[nt][1] + bb.y;
            float o2 = acc[nt][2] + bb.x, o3 = acc[nt][3] + bb.y;
            if (fk == 0) {
                if (r < NN)
                    *reinterpret_cast<float2*>(g_H0 + (size_t)r * HID + c) = make_float2(o0, o1);
                if (r2 < NN)
                    *reinterpret_cast<float2*>(g_H0 + (size_t)r2 * HID + c) = make_float2(o2, o3);
            } else {
                if (r < NN)  G[r * 32 + (c >> 1)]  = __floats2half2_rn(o0, o1);
                if (r2 < NN) G[r2 * 32 + (c >> 1)] = __floats2half2_rn(o2, o3);
            }
            pa  += o0 * wt.x + o1 * wt.y;  pb  += o0 * wb.x + o1 * wb.y;
            pa2 += o2 * wt.x + o3 * wt.y;  pb2 += o2 * wb.x + o3 * wb.y;
        }
#pragma unroll
        for (int off = 1; off <= 2; off <<= 1) {
            pa  += __shfl_xor_sync(0xffffffffu, pa,  off);
            pb  += __shfl_xor_sync(0xffffffffu, pb,  off);
            pa2 += __shfl_xor_sync(0xffffffffu, pa2, off);
            pb2 += __shfl_xor_sync(0xffffffffu, pb2, off);
        }
        if (qk == 0) {
            if (r < NN) {
                if (fk == 0)      g_s00[r] = pa + pb * (1.0f / 3.0f) + ba;
                else if (fk == 1) g_sb1[r] = pb * (1.0f / 3.0f);
                else              g_sb2[r] = pb * (1.0f / 3.0f);
            }
            if (r2 < NN) {
                if (fk == 0)      g_s00[r2] = pa2 + pb2 * (1.0f / 3.0f) + ba;
                else if (fk == 1) g_sb1[r2] = pb2 * (1.0f / 3.0f);
                else              g_sb2[r2] = pb2 * (1.0f / 3.0f);
            }
        }
    }
}

// ---------------- kernel 2: degree histogram (deg pre-zeroed by agg tail) --------
__global__ void hist_kernel(const int* __restrict__ e0) {
    int i = blockIdx.x * blockDim.x + threadIdx.x;
    if (i < NE / 4) {
        int4 v = reinterpret_cast<const int4*>(e0)[i];
        atomicAdd(&g_deg[v.x], 1);
        atomicAdd(&g_deg[v.y], 1);
        atomicAdd(&g_deg[v.z], 1);
        atomicAdd(&g_deg[v.w], 1);
    }
}

// ---------------- kernel 3a: block-local scan, write partials ----------------
__global__ void scan1_kernel() {
    __shared__ int s[1024];
    int i = blockIdx.x * 1024 + threadIdx.x;
    int v = (i < NN) ? g_deg[i] : 0;
    s[threadIdx.x] = v;
    __syncthreads();
    for (int off = 1; off < 1024; off <<= 1) {
        int t = (threadIdx.x >= (unsigned)off) ? s[threadIdx.x - off] : 0;
        __syncthreads();
        s[threadIdx.x] += t;
        __syncthreads();
    }
    if (i < NN) g_offs[i] = s[threadIdx.x] - v;
    if (threadIdx.x == 1023) g_part[blockIdx.x] = s[1023];
}
// ---------------- kernel 3b: each block scans partials itself, adds prefix -------
__global__ void scan3_kernel() {
    __shared__ int s[128];
    int v = (threadIdx.x < NPART) ? g_part[threadIdx.x] : 0;
    s[threadIdx.x] = v;
    __syncthreads();
    for (int off = 1; off < 128; off <<= 1) {
        int t = (threadIdx.x >= (unsigned)off) ? s[threadIdx.x - off] : 0;
        __syncthreads();
        s[threadIdx.x] += t;
        __syncthreads();
    }
    __shared__ int prefix;
    if (threadIdx.x == (unsigned)blockIdx.x) prefix = s[threadIdx.x] - v;  // exclusive
    __syncthreads();
    int p = prefix;
#pragma unroll
    for (int q = 0; q < 8; q++) {
        int i = blockIdx.x * 1024 + q * 128 + threadIdx.x;
        if (i < NN) g_offs[i] += p;
    }
}

// ---------------- kernel 4: edge pass — pure CSR scatter of {i1,i2} --------------
__global__ void edge_kernel(const int* __restrict__ e0, const int* __restrict__ e1,
                            const int* __restrict__ e2) {
    int i = blockIdx.x * blockDim.x + threadIdx.x;
    if (i >= NE / 4) return;
    int4 a = reinterpret_cast<const int4*>(e0)[i];
    int4 b = reinterpret_cast<const int4*>(e1)[i];
    int4 c = reinterpret_cast<const int4*>(e2)[i];
#pragma unroll
    for (int q = 0; q < 4; q++) {
        int n  = (q == 0) ? a.x : (q == 1) ? a.y : (q == 2) ? a.z : a.w;
        int i1 = (q == 0) ? b.x : (q == 1) ? b.y : (q == 2) ? b.z : b.w;
        int i2 = (q == 0) ? c.x : (q == 1) ? c.y : (q == 2) ? c.z : c.w;
        int p = atomicAdd(&g_offs[n], 1);
        g_epack[p] = make_int2(i1, i2);
    }
}

// ---------------- kernel 5: aggregate — scores fused, batched prefetch + shfl ----
__global__ __launch_bounds__(256) void agg_kernel(const float* __restrict__ bias,
                                                  float* __restrict__ out) {
    int gw = (blockIdx.x * 256 + threadIdx.x) >> 5;
    int lane = threadIdx.x & 31;
    if (gw >= NN) return;
    int d = g_deg[gw];
    int start = g_offs[gw] - d;   // offs is end-offset after edge pass
    float2 bz = *reinterpret_cast<const float2*>(&bias[2 * lane]);
    float2 o;
    if (d == 0) {
        o = bz;
    } else {
        float s00 = g_s00[gw];    // once per node (broadcast load)
        float2 acc = make_float2(0.f, 0.f);
        float sumex = 0.f;
        for (int base = 0; base < d; base += 32) {
            int m = min(32, d - base);
            float myex = 0.f;
            int myi1 = 0, myi2 = 0;
            if (lane < m) {
                int2 rec = g_epack[start + base + lane];
                myi1 = rec.x;
                myi2 = rec.y;
                myex = __expf(tanh_approx(s00 + g_sb1[myi1] + g_sb2[myi2]));
            }
#pragma unroll 4
            for (int j = 0; j < m; j++) {
                float ex = __shfl_sync(0xffffffffu, myex, j);
                int i1   = __shfl_sync(0xffffffffu, myi1, j);
                int i2   = __shfl_sync(0xffffffffu, myi2, j);
                float2 f1 = __half22float2(g_G1[i1 * 32 + lane]);
                float2 f2 = __half22float2(g_G2[i2 * 32 + lane]);
                sumex += ex;
                acc.x += ex * (f1.x + f2.x);
                acc.y += ex * (f1.y + f2.y);
            }
        }
        float2 h0 = *reinterpret_cast<const float2*>(&g_H0[gw * HID + 2 * lane]);
        float inv = 1.0f / sumex;
        o.x = (h0.x + acc.x * inv) * (1.0f / 3.0f) + bz.x;
        o.y = (h0.y + acc.y * inv) * (1.0f / 3.0f) + bz.y;
    }
    *reinterpret_cast<float2*>(&out[gw * HID + 2 * lane]) = o;
    if (lane == 0) g_deg[gw] = 0;   // restore invariant for next replay
}

// ---------------- launch (fork-join: CSR chain overlaps GEMM) ----------------
extern "C" void kernel_launch(void* const* d_in, const int* in_sizes, int n_in,
                              void* d_out, int out_size) {
    const float* feats[3] = {0, 0, 0};
    const int* edges[3] = {0, 0, 0};
    const float *W_feat = 0, *b_feat = 0, *W_att = 0, *b_att = 0, *bias = 0;
    int nf = 0, ne = 0;
    for (int i = 0; i < n_in; i++) {
        int s = in_sizes[i];
        if (s == NN * KF) { if (nf < 3) feats[nf++] = (const float*)d_in[i]; }
        else if (s == NE) { if (ne < 3) edges[ne++] = (const int*)d_in[i]; }
        else if (s == KF * HID) W_feat = (const float*)d_in[i];
        else if (s == 2 * HID) W_att = (const float*)d_in[i];
        else if (s == HID) { if (!b_feat) b_feat = (const float*)d_in[i]; else bias = (const float*)d_in[i]; }
        else if (s == 1) b_att = (const float*)d_in[i];
    }
    float* out = (float*)d_out;

    static cudaStream_t s2 = 0;
    static cudaEvent_t ev_fork = 0, ev_join = 0;
    if (!s2) {
        cudaStreamCreateWithFlags(&s2, cudaStreamNonBlocking);
        cudaEventCreateWithFlags(&ev_fork, cudaEventDisableTiming);
        cudaEventCreateWithFlags(&ev_join, cudaEventDisableTiming);
    }

    // fork: CSR chain on s2 (depends only on edge0; deg==0 invariant from agg tail)
    cudaEventRecord(ev_fork, 0);
    cudaStreamWaitEvent(s2, ev_fork, 0);
    hist_kernel<<<(NE / 4 + 255) / 256, 256, 0, s2>>>(edges[0]);
    scan1_kernel<<<NPART, 1024, 0, s2>>>();
    scan3_kernel<<<NPART, 128, 0, s2>>>();
    cudaEventRecord(ev_join, s2);

    // main stream: GEMM (depends only on feats/W)
    int gx = (NN + 64 * GTILES - 1) / (64 * GTILES);
    gemm_mma_kernel<<<dim3(gx, 3), 128>>>(
        feats[0], feats[1], feats[2], W_feat, b_feat, W_att, b_att);

    // join, then edge + agg
    cudaStreamWaitEvent(0, ev_join, 0);
    edge_kernel<<<(NE / 4 + 255) / 256, 256>>>(edges[0], edges[1], edges[2]);
    agg_kernel<<<(NN * 32 + 255) / 256, 256>>>(bias, out);
}

// round 15
// speedup vs baseline: 1.3674x; 1.0145x over previous
#include <cuda_runtime.h>
#include <cuda_fp16.h>
#include <cstdint>

#define NN 100000
#define NE 1000000
#define KF 128
#define HID 64
#define GTILES 8                      // row-tiles (64 rows) per GEMM block
#define NPART 98                      // scan partial blocks = ceil(NN/1024)
#define WT_STRIDE 132                 // 132 mod 32 == 4 -> W frag loads conflict-free

// ---------------- scratch ----------------
__device__ float   g_H0[NN * HID];     // f32: exact per-node term
__device__ __half2 g_G1[NN * 32];      // H1 rows as 32 half2 (col pairs)
__device__ __half2 g_G2[NN * 32];      // H2 rows as 32 half2
__device__ float g_s00[NN];            // H0.Wa_top + H0.Wa_bot/3 + b_att
__device__ float g_sb1[NN];            // H1.Wa_bot/3
__device__ float g_sb2[NN];            // H2.Wa_bot/3
__device__ int   g_deg[NN];            // INVARIANT: zero at entry (agg re-zeroes)
__device__ int   g_offs[NN];           // exclusive offsets; end-offsets after edge pass
__device__ int   g_part[128];
__device__ int2  g_epack[NE];          // {i1, i2} in CSR order

// ---------------- helpers ----------------
__device__ __forceinline__ uint32_t tf32_rna(float x) {
    uint32_t u;
    asm("cvt.rna.tf32.f32 %0, %1;" : "=r"(u) : "f"(x));
    return u;
}
__device__ __forceinline__ float tanh_approx(float x) {
    float t;
    asm("tanh.approx.f32 %0, %1;" : "=f"(t) : "f"(x));
    return t;
}
__device__ __forceinline__ void cpa16(void* smem, const void* gmem) {
    unsigned s = (unsigned)__cvta_generic_to_shared(smem);
    asm volatile("cp.async.ca.shared.global [%0], [%1], 16;\n" :: "r"(s), "l"(gmem));
}

// ---------------- kernel 1: tf32 mma.sync GEMM (warp-private A tiles) ------------
// 128 threads = 4 warps; per tile 64 rows x 64 cols; K=128, 16 chunks of 8.
// Warp w writes AND reads only As rows [16w,16w+16) -> mainloop needs only
// __syncwarp (cp.async wait_group is per-thread; syncwarp orders lane writes).
__global__ void __launch_bounds__(128) gemm_mma_kernel(
    const float* __restrict__ f0, const float* __restrict__ f1,
    const float* __restrict__ f2, const float* __restrict__ W,
    const float* __restrict__ b, const float* __restrict__ Wa,
    const float* __restrict__ b_att)
{
    __shared__ uint32_t Wst[HID][WT_STRIDE];   // tf32 W^T[n][k]; frag bank=(4qr+qk): conflict-free
    __shared__ float As[4][64][12];            // conflict-free (12qr+qk distinct mod 32)

    int fk = blockIdx.y;
    const float* feat = (fk == 0) ? f0 : ((fk == 1) ? f1 : f2);
    int tid = threadIdx.x;
    int wid = tid >> 5, lane = tid & 31;
    int qk = lane & 3;
    int qr = lane >> 2;
    int wl = wid * 16 + qr;
    int crow = tid >> 1, ccol4 = tid & 1;
    float ba = (fk == 0) ? __ldg(b_att) : 0.f;
    __half2* G = (fk == 1) ? g_G1 : g_G2;

    // stage W transposed (tf32-rounded) once per block; coalesced global reads
#pragma unroll
    for (int i = 0; i < 64; i++) {
        int idx = tid + i * 128;               // 0..8191 over W[k][n]
        Wst[idx & 63][idx >> 6] = tf32_rna(W[idx]);
    }
    __syncthreads();   // Wst is cross-warp shared (read-only after this)

    for (int t = 0; t < GTILES; t++) {
        int row0 = (blockIdx.x * GTILES + t) * 64;
        if (row0 >= NN) break;

        int gr = row0 + crow;
        if (gr >= NN) gr = NN - 1;
        const float* csrc = feat + (size_t)gr * KF + ccol4 * 4;
        auto issue = [&](int c) {
            cpa16(&As[c & 3][crow][ccol4 * 4], csrc + c * 8);
            asm volatile("cp.async.commit_group;\n");
        };

        issue(0); issue(1); issue(2);

        float acc[8][4];
#pragma unroll
        for (int nt = 0; nt < 8; nt++)
#pragma unroll
            for (int j = 0; j < 4; j++) acc[nt][j] = 0.f;

#pragma unroll
        for (int c = 0; c < 16; c++) {
            if (c < 14)       asm volatile("cp.async.wait_group 2;\n");
            else if (c == 14) asm volatile("cp.async.wait_group 1;\n");
            else              asm volatile("cp.async.wait_group 0;\n");
            __syncwarp();   // As rows are warp-private; no block barrier needed
            if (c + 3 < 16) issue(c + 3);
            int buf = c & 3;
            uint32_t a0 = tf32_rna(As[buf][wl][qk]);
            uint32_t a1 = tf32_rna(As[buf][wl + 8][qk]);
            uint32_t a2 = tf32_rna(As[buf][wl][qk + 4]);
            uint32_t a3 = tf32_rna(As[buf][wl + 8][qk + 4]);
            int k0 = c * 8;
#pragma unroll
            for (int nt = 0; nt < 8; nt++) {
                uint32_t b0 = Wst[nt * 8 + qr][k0 + qk];
                uint32_t b1 = Wst[nt * 8 + qr][k0 + qk + 4];
                asm volatile(
                    "mma.sync.aligned.m16n8k8.row.col.f32.tf32.tf32.f32 "
                    "{%0,%1,%2,%3}, {%4,%5,%6,%7}, {%8,%9}, {%0,%1,%2,%3};"
                    : "+f"(acc[nt][0]), "+f"(acc[nt][1]), "+f"(acc[nt][2]), "+f"(acc[nt][3])
                    : "r"(a0), "r"(a1), "r"(a2), "r"(a3), "r"(b0), "r"(b1));
            }
        }

        int r  = row0 + wl;
        int r2 = r + 8;
        float pa = 0.f, pb = 0.f, pa2 = 0.f, pb2 = 0.f;
#pragma unroll
        for (int nt = 0; nt < 8; nt++) {
            int c = nt * 8 + 2 * qk;
            float2 bb = *reinterpret_cast<const float2*>(b + c);
            float2 wt = *reinterpret_cast<const float2*>(Wa + c);
            float2 wb = *reinterpret_cast<const float2*>(Wa + 64 + c);
            float o0 = acc[nt][0] + bb.x, o1 = acc[nt][1] + bb.y;
            float o2 = acc[nt][2] + bb.x, o3 = acc[nt][3] + bb.y;
            if (fk == 0) {
                if (r < NN)
                    *reinterpret_cast<float2*>(g_H0 + (size_t)r * HID + c) = make_float2(o0, o1);
                if (r2 < NN)
                    *reinterpret_cast<float2*>(g_H0 + (size_t)r2 * HID + c) = make_float2(o2, o3);
            } else {
                if (r < NN)  G[r * 32 + (c >> 1)]  = __floats2half2_rn(o0, o1);
                if (r2 < NN) G[r2 * 32 + (c >> 1)] = __floats2half2_rn(o2, o3);
            }
            pa  += o0 * wt.x + o1 * wt.y;  pb  += o0 * wb.x + o1 * wb.y;
            pa2 += o2 * wt.x + o3 * wt.y;  pb2 += o2 * wb.x + o3 * wb.y;
        }
#pragma unroll
        for (int off = 1; off <= 2; off <<= 1) {
            pa  += __shfl_xor_sync(0xffffffffu, pa,  off);
            pb  += __shfl_xor_sync(0xffffffffu, pb,  off);
            pa2 += __shfl_xor_sync(0xffffffffu, pa2, off);
            pb2 += __shfl_xor_sync(0xffffffffu, pb2, off);
        }
        if (qk == 0) {
            if (r < NN) {
                if (fk == 0)      g_s00[r] = pa + pb * (1.0f / 3.0f) + ba;
                else if (fk == 1) g_sb1[r] = pb * (1.0f / 3.0f);
                else              g_sb2[r] = pb * (1.0f / 3.0f);
            }
            if (r2 < NN) {
                if (fk == 0)      g_s00[r2] = pa2 + pb2 * (1.0f / 3.0f) + ba;
                else if (fk == 1) g_sb1[r2] = pb2 * (1.0f / 3.0f);
                else              g_sb2[r2] = pb2 * (1.0f / 3.0f);
            }
        }
    }
}

// ---------------- kernel 2: degree histogram (deg pre-zeroed by agg tail) --------
__global__ void hist_kernel(const int* __restrict__ e0) {
    int i = blockIdx.x * blockDim.x + threadIdx.x;
    if (i < NE / 4) {
        int4 v = reinterpret_cast<const int4*>(e0)[i];
        atomicAdd(&g_deg[v.x], 1);
        atomicAdd(&g_deg[v.y], 1);
        atomicAdd(&g_deg[v.z], 1);
        atomicAdd(&g_deg[v.w], 1);
    }
}

// ---------------- kernel 3a: block-local scan, write partials ----------------
__global__ void scan1_kernel() {
    __shared__ int s[1024];
    int i = blockIdx.x * 1024 + threadIdx.x;
    int v = (i < NN) ? g_deg[i] : 0;
    s[threadIdx.x] = v;
    __syncthreads();
    for (int off = 1; off < 1024; off <<= 1) {
        int t = (threadIdx.x >= (unsigned)off) ? s[threadIdx.x - off] : 0;
        __syncthreads();
        s[threadIdx.x] += t;
        __syncthreads();
    }
    if (i < NN) g_offs[i] = s[threadIdx.x] - v;
    if (threadIdx.x == 1023) g_part[blockIdx.x] = s[1023];
}
// ---------------- kernel 3b: each block scans partials itself, adds prefix -------
__global__ void scan3_kernel() {
    __shared__ int s[128];
    int v = (threadIdx.x < NPART) ? g_part[threadIdx.x] : 0;
    s[threadIdx.x] = v;
    __syncthreads();
    for (int off = 1; off < 128; off <<= 1) {
        int t = (threadIdx.x >= (unsigned)off) ? s[threadIdx.x - off] : 0;
        __syncthreads();
        s[threadIdx.x] += t;
        __syncthreads();
    }
    __shared__ int prefix;
    if (threadIdx.x == (unsigned)blockIdx.x) prefix = s[threadIdx.x] - v;  // exclusive
    __syncthreads();
    int p = prefix;
#pragma unroll
    for (int q = 0; q < 8; q++) {
        int i = blockIdx.x * 1024 + q * 128 + threadIdx.x;
        if (i < NN) g_offs[i] += p;
    }
}

// ---------------- kernel 4: edge pass — pure CSR scatter of {i1,i2} --------------
__global__ void edge_kernel(const int* __restrict__ e0, const int* __restrict__ e1,
                            const int* __restrict__ e2) {
    int i = blockIdx.x * blockDim.x + threadIdx.x;
    if (i >= NE / 4) return;
    int4 a = reinterpret_cast<const int4*>(e0)[i];
    int4 b = reinterpret_cast<const int4*>(e1)[i];
    int4 c = reinterpret_cast<const int4*>(e2)[i];
#pragma unroll
    for (int q = 0; q < 4; q++) {
        int n  = (q == 0) ? a.x : (q == 1) ? a.y : (q == 2) ? a.z : a.w;
        int i1 = (q == 0) ? b.x : (q == 1) ? b.y : (q == 2) ? b.z : b.w;
        int i2 = (q == 0) ? c.x : (q == 1) ? c.y : (q == 2) ? c.z : c.w;
        int p = atomicAdd(&g_offs[n], 1);
        g_epack[p] = make_int2(i1, i2);
    }
}

// ---------------- kernel 5: aggregate — scores fused, batched prefetch + shfl ----
__global__ __launch_bounds__(256) void agg_kernel(const float* __restrict__ bias,
                                                  float* __restrict__ out) {
    int gw = (blockIdx.x * 256 + threadIdx.x) >> 5;
    int lane = threadIdx.x & 31;
    if (gw >= NN) return;
    int d = g_deg[gw];
    int start = g_offs[gw] - d;   // offs is end-offset after edge pass
    float2 bz = *reinterpret_cast<const float2*>(&bias[2 * lane]);
    float2 o;
    if (d == 0) {
        o = bz;
    } else {
        float s00 = g_s00[gw];    // once per node (broadcast load)
        float2 acc = make_float2(0.f, 0.f);
        float sumex = 0.f;
        for (int base = 0; base < d; base += 32) {
            int m = min(32, d - base);
            float myex = 0.f;
            int myi1 = 0, myi2 = 0;
            if (lane < m) {
                int2 rec = g_epack[start + base + lane];
                myi1 = rec.x;
                myi2 = rec.y;
                myex = __expf(tanh_approx(s00 + g_sb1[myi1] + g_sb2[myi2]));
            }
#pragma unroll 4
            for (int j = 0; j < m; j++) {
                float ex = __shfl_sync(0xffffffffu, myex, j);
                int i1   = __shfl_sync(0xffffffffu, myi1, j);
                int i2   = __shfl_sync(0xffffffffu, myi2, j);
                float2 f1 = __half22float2(g_G1[i1 * 32 + lane]);
                float2 f2 = __half22float2(g_G2[i2 * 32 + lane]);
                sumex += ex;
                acc.x += ex * (f1.x + f2.x);
                acc.y += ex * (f1.y + f2.y);
            }
        }
        float2 h0 = *reinterpret_cast<const float2*>(&g_H0[gw * HID + 2 * lane]);
        float inv = 1.0f / sumex;
        o.x = (h0.x + acc.x * inv) * (1.0f / 3.0f) + bz.x;
        o.y = (h0.y + acc.y * inv) * (1.0f / 3.0f) + bz.y;
    }
    *reinterpret_cast<float2*>(&out[gw * HID + 2 * lane]) = o;
    if (lane == 0) g_deg[gw] = 0;   // restore invariant for next replay
}

// ---------------- launch (fork-join: CSR chain overlaps GEMM) ----------------
extern "C" void kernel_launch(void* const* d_in, const int* in_sizes, int n_in,
                              void* d_out, int out_size) {
    const float* feats[3] = {0, 0, 0};
    const int* edges[3] = {0, 0, 0};
    const float *W_feat = 0, *b_feat = 0, *W_att = 0, *b_att = 0, *bias = 0;
    int nf = 0, ne = 0;
    for (int i = 0; i < n_in; i++) {
        int s = in_sizes[i];
        if (s == NN * KF) { if (nf < 3) feats[nf++] = (const float*)d_in[i]; }
        else if (s == NE) { if (ne < 3) edges[ne++] = (const int*)d_in[i]; }
        else if (s == KF * HID) W_feat = (const float*)d_in[i];
        else if (s == 2 * HID) W_att = (const float*)d_in[i];
        else if (s == HID) { if (!b_feat) b_feat = (const float*)d_in[i]; else bias = (const float*)d_in[i]; }
        else if (s == 1) b_att = (const float*)d_in[i];
    }
    float* out = (float*)d_out;

    static cudaStream_t s2 = 0;
    static cudaEvent_t ev_fork = 0, ev_join = 0;
    if (!s2) {
        cudaStreamCreateWithFlags(&s2, cudaStreamNonBlocking);
        cudaEventCreateWithFlags(&ev_fork, cudaEventDisableTiming);
        cudaEventCreateWithFlags(&ev_join, cudaEventDisableTiming);
    }

    // fork: CSR chain on s2 (depends only on edge0; deg==0 invariant from agg tail)
    cudaEventRecord(ev_fork, 0);
    cudaStreamWaitEvent(s2, ev_fork, 0);
    hist_kernel<<<(NE / 4 + 255) / 256, 256, 0, s2>>>(edges[0]);
    scan1_kernel<<<NPART, 1024, 0, s2>>>();
    scan3_kernel<<<NPART, 128, 0, s2>>>();
    cudaEventRecord(ev_join, s2);

    // main stream: GEMM (depends only on feats/W)
    int gx = (NN + 64 * GTILES - 1) / (64 * GTILES);
    gemm_mma_kernel<<<dim3(gx, 3), 128>>>(
        feats[0], feats[1], feats[2], W_feat, b_feat, W_att, b_att);

    // join, then edge + agg
    cudaStreamWaitEvent(0, ev_join, 0);
    edge_kernel<<<(NE / 4 + 255) / 256, 256>>>(edges[0], edges[1], edges[2]);
    agg_kernel<<<(NN * 32 + 255) / 256, 256>>>(bias, out);
}